// round 15
// baseline (speedup 1.0000x reference)
#include <cuda_runtime.h>
#include <math.h>
#include <stdint.h>
#include <mma.h>

using namespace nvcuda;

// Problem constants
#define NTOT 50000
#define EDIM 1000
#define DM   256
#define HEADS 4
#define MF   30
#define LNUM 3
#define NF   (HEADS * MF)          // 120 feature columns
#define NQK  (2 * NF)              // 240 logical [Qp | Kp] columns
#define NQKP 256                   // padded row stride of QKp

// ---------------------------------------------------------------------------
// Scratch (device globals — no allocations allowed)
// ---------------------------------------------------------------------------
__device__ float g_z  [NTOT * DM];          // ln output
__device__ float g_QKp[NTOT * NQKP];        // [Qp | Kp | pad] features
__device__ float g_Qps[NTOT * NF];          // Qp / den
__device__ float g_S  [NF * DM];            // Kp^T @ z
__device__ float g_Ks [NF];                 // sum_n Kp
__device__ float g_KV [NF * DM];            // S @ Wv + Ks (x) bv
__device__ float g_W2t[DM * NF];            // (KV @ Wo)^T  [256 x 120]
__device__ float g_BR [8 * 16 * 256];       // 16-row replicated biases
// transposed / folded weights
__device__ float g_WT[506576];

#define WT_IN   0
#define WT_HE   65536
#define WQK(l)  (321536 + (l) * 61440)      // 240 rows x 256 (rows 0-119 Q, 120-239 K)
#define BQK(l)  (505856 + (l) * 240)
#define BR_V(v) ((v) * 16 * 256)            // 0 b_in, 1 b_he, 2+l bqk, 5+l bo

// ---------------------------------------------------------------------------
// cp.async helpers (base ISA, sm_80+)
// ---------------------------------------------------------------------------
__device__ __forceinline__ uint32_t smem_u32(const void* p) {
    uint32_t a;
    asm("{ .reg .u64 t; cvta.to.shared.u64 t, %1; cvt.u32.u64 %0, t; }"
        : "=r"(a) : "l"(p));
    return a;
}

__device__ __forceinline__ void cpasync16(uint32_t dst, const void* src, int srcsize) {
    asm volatile("cp.async.cg.shared.global [%0], [%1], 16, %2;"
        :: "r"(dst), "l"(src), "r"(srcsize) : "memory");
}
#define CP_COMMIT() asm volatile("cp.async.commit_group;" ::: "memory")
#define CP_WAIT2()  asm volatile("cp.async.wait_group 2;" ::: "memory")

// ---------------------------------------------------------------------------
// WMMA TF32 GEMM: C[M x Nn-ish] = A[M x K] @ Bt^T + bias (+C) (or exp)
//   A  : [M, K]  row-major fp32 (row stride == K)
//   Bt : [Nn, K] row-major fp32 (K-major == wmma col_major B); rows >= Nn read 0
//   biasRep : 16-row replicated bias [16 x 256]
//   Block tile 128 x 128, BK = 32, 8 warps (warp tile 64 x 32), 3-stage pipe.
//   C always written 128 cols wide (buffers padded to Cstride >= col0+128).
//   mode: 0 = C = v + bias ; 1 = C += v + bias ; 2 = C = exp(v + bias) + 1e-6
// ---------------------------------------------------------------------------
#define BK 32
#define ROWF 36
#define STAGE_F (2 * 128 * ROWF)            // 9216 floats = 36864 B per stage
#define GEMM_SMEM (3 * STAGE_F * 4)         // 110592 B

__global__ __launch_bounds__(256, 2)
void gemm_tc(const float* __restrict__ A, const float* __restrict__ Bt,
             float* __restrict__ C, const float* __restrict__ biasRep,
             int M, int Nn, int K, int Cstride, int mode)
{
    extern __shared__ __align__(16) float smem[];

    const int tid  = threadIdx.x;
    const int wid  = tid >> 5;
    const int wm   = wid & 1;          // 0..1 -> 64-row slab
    const int wn   = wid >> 1;         // 0..3 -> 32-col slab
    const int row0 = blockIdx.y * 128;
    const int col0 = blockIdx.x * 128;

    const int T = (K + BK - 1) / BK;

    wmma::fragment<wmma::accumulator, 16, 16, 8, float> acc[4][2];
#pragma unroll
    for (int i = 0; i < 4; i++)
#pragma unroll
        for (int j = 0; j < 2; j++) wmma::fill_fragment(acc[i][j], 0.f);

    auto load_tile = [&](int tt, int ss) {
        float* As = smem + ss * STAGE_F;
        float* Bs = As + 128 * ROWF;
        const uint32_t asb = smem_u32(As);
        const uint32_t bsb = smem_u32(Bs);
        const int kbase = tt * BK;
#pragma unroll
        for (int i = 0; i < 4; i++) {          // A: 1024 16B chunks
            const int id  = tid + i * 256;
            const int row = id >> 3, c = id & 7;
            const int gr = row0 + row;
            const int gk = kbase + c * 4;
            const int ok = (gr < M) && (gk + 4 <= K);
            const float* src = ok ? (A + (size_t)gr * K + gk) : A;
            cpasync16(asb + (row * ROWF + c * 4) * 4, src, ok ? 16 : 0);
        }
#pragma unroll
        for (int i = 0; i < 4; i++) {          // B: 1024 16B chunks
            const int id  = tid + i * 256;
            const int row = id >> 3, c = id & 7;
            const int gn = col0 + row;
            const int gk = kbase + c * 4;
            const int ok = (gn < Nn) && (gk + 4 <= K);
            const float* src = ok ? (Bt + (size_t)gn * K + gk) : Bt;
            cpasync16(bsb + (row * ROWF + c * 4) * 4, src, ok ? 16 : 0);
        }
    };

    // 3-stage prologue
    load_tile(0, 0);
    CP_COMMIT();
    if (T > 1) load_tile(1, 1);
    CP_COMMIT();

    for (int t = 0; t < T; t++) {
        if (t + 2 < T) load_tile(t + 2, (t + 2) % 3);
        CP_COMMIT();
        CP_WAIT2();
        __syncthreads();

        const float* As = smem + (t % 3) * STAGE_F;
        const float* Bs = As + 128 * ROWF;

#pragma unroll
        for (int ks = 0; ks < 4; ks++) {
            const int k0 = ks * 8;
            wmma::fragment<wmma::matrix_a, 16, 16, 8, wmma::precision::tf32,
                           wmma::row_major> af[4];
            wmma::fragment<wmma::matrix_b, 16, 16, 8, wmma::precision::tf32,
                           wmma::col_major> bf[2];
#pragma unroll
            for (int i = 0; i < 4; i++) {
                wmma::load_matrix_sync(af[i], As + (wm * 64 + i * 16) * ROWF + k0, ROWF);
#pragma unroll
                for (int e = 0; e < af[i].num_elements; e++)
                    af[i].x[e] = wmma::__float_to_tf32(af[i].x[e]);
            }
#pragma unroll
            for (int j = 0; j < 2; j++) {
                wmma::load_matrix_sync(bf[j], Bs + (wn * 32 + j * 16) * ROWF + k0, ROWF);
#pragma unroll
                for (int e = 0; e < bf[j].num_elements; e++)
                    bf[j].x[e] = wmma::__float_to_tf32(bf[j].x[e]);
            }
#pragma unroll
            for (int i = 0; i < 4; i++)
#pragma unroll
                for (int j = 0; j < 2; j++)
                    wmma::mma_sync(acc[i][j], af[i], bf[j], acc[i][j]);
        }
        __syncthreads();
    }

    // ---- epilogue ----
    const bool tail = (row0 + 128 > M);
    if (!tail) {
        // direct fragment path: bias via accumulator-layout fragment
        wmma::fragment<wmma::accumulator, 16, 16, 8, float> bfr[2];
#pragma unroll
        for (int j = 0; j < 2; j++)
            wmma::load_matrix_sync(bfr[j], biasRep + col0 + wn * 32 + j * 16, 256,
                                   wmma::mem_row_major);
#pragma unroll
        for (int i = 0; i < 4; i++) {
            const int gr0 = row0 + wm * 64 + i * 16;
#pragma unroll
            for (int j = 0; j < 2; j++) {
                const int gc0 = col0 + wn * 32 + j * 16;
                float* cp = C + (size_t)gr0 * Cstride + gc0;
                if (mode == 1) {
                    wmma::fragment<wmma::accumulator, 16, 16, 8, float> cf;
                    wmma::load_matrix_sync(cf, cp, Cstride, wmma::mem_row_major);
#pragma unroll
                    for (int e = 0; e < cf.num_elements; e++)
                        acc[i][j].x[e] += bfr[j].x[e] + cf.x[e];
                } else if (mode == 2) {
#pragma unroll
                    for (int e = 0; e < bfr[j].num_elements; e++)
                        acc[i][j].x[e] = __expf(acc[i][j].x[e] + bfr[j].x[e]) + 1e-6f;
                } else {
#pragma unroll
                    for (int e = 0; e < bfr[j].num_elements; e++)
                        acc[i][j].x[e] += bfr[j].x[e];
                }
                wmma::store_matrix_sync(cp, acc[i][j], Cstride, wmma::mem_row_major);
            }
        }
    } else {
        // staged fallback for the M-tail block (reuses stage smem)
        float* Cs = smem;                  // 128 x 132
#pragma unroll
        for (int i = 0; i < 4; i++)
#pragma unroll
            for (int j = 0; j < 2; j++)
                wmma::store_matrix_sync(Cs + (wm * 64 + i * 16) * 132 + wn * 32 + j * 16,
                                        acc[i][j], 132, wmma::mem_row_major);
        __syncthreads();

        const int r    = tid >> 1;
        const int half = tid & 1;
        const int gr   = row0 + r;
        if (gr < M) {
            const float* sp = Cs + r * 132 + half * 64;
#pragma unroll
            for (int j = 0; j < 16; j++) {
                const int cc = col0 + half * 64 + j * 4;
                float4 v = *(const float4*)(sp + j * 4);
                float4 bv = *(const float4*)(biasRep + cc);
                v.x += bv.x; v.y += bv.y; v.z += bv.z; v.w += bv.w;
                float* cp = C + (size_t)gr * Cstride + cc;
                if (mode == 1) {
                    float4 o = *(float4*)cp;
                    v.x += o.x; v.y += o.y; v.z += o.z; v.w += o.w;
                } else if (mode == 2) {
                    v.x = __expf(v.x) + 1e-6f; v.y = __expf(v.y) + 1e-6f;
                    v.z = __expf(v.z) + 1e-6f; v.w = __expf(v.w) + 1e-6f;
                }
                *(float4*)cp = v;
            }
        }
    }
}

// ---------------------------------------------------------------------------
// Mega-transpose (W_in, W_he only): out[Nn x K] = in[K x Nn]^T
// ---------------------------------------------------------------------------
__global__ void mega_transpose(const float* __restrict__ W_in,
                               const float* __restrict__ W_he,
                               float* __restrict__ WT)
{
    const int z = blockIdx.z;
    const float* src; float* dst; int K, Nn;
    if (z == 0) { src = W_in; dst = WT + WT_IN; K = 256;  Nn = 256; }
    else        { src = W_he; dst = WT + WT_HE; K = EDIM; Nn = 256; }

    const int k0 = blockIdx.x * 32, n0 = blockIdx.y * 32;
    if (k0 >= K || n0 >= Nn) return;

    __shared__ float tile[32][33];
    const int tx = threadIdx.x, ty = threadIdx.y;
#pragma unroll
    for (int r = 0; r < 4; r++) {
        const int k = k0 + ty + r * 8;
        if (k < K && n0 + tx < Nn) tile[ty + r * 8][tx] = src[(size_t)k * Nn + n0 + tx];
    }
    __syncthreads();
#pragma unroll
    for (int r = 0; r < 4; r++) {
        const int n = n0 + ty + r * 8;
        if (n < Nn && k0 + tx < K) dst[(size_t)n * K + k0 + tx] = tile[tx][ty + r * 8];
    }
}

// ---------------------------------------------------------------------------
// Mega-fold: FAVOR+ weight folds, grid (NF, 2, LNUM); y=0 -> Q, y=1 -> K
// ---------------------------------------------------------------------------
__global__ __launch_bounds__(256)
void mega_fold(const float* __restrict__ Wq, const float* __restrict__ bq,
               const float* __restrict__ Wk, const float* __restrict__ bk,
               const float* __restrict__ proj, float* __restrict__ WT)
{
    __shared__ float ps[DM];
    const int l   = blockIdx.z;
    const int isK = blockIdx.y;
    const float* W = (isK ? Wk : Wq) + (size_t)l * DM * HEADS * DM;
    const float* b = (isK ? bk : bq) + (size_t)l * (HEADS * DM);
    float* Wout = WT + WQK(l) + isK * (NF * DM);
    float* bout = WT + BQK(l) + isK * NF;

    const int nn = blockIdx.x;       // 0..119
    const int h = nn / MF, m = nn % MF;
    const int k = threadIdx.x;       // 0..255
    const float c = 0.25f * 0.18257418583505536f;
    ps[k] = c * proj[(size_t)m * DM + k];
    __syncthreads();

    float s = 0.f;
    const float* wp = W + (size_t)k * (HEADS * DM) + h * DM;
#pragma unroll 8
    for (int d = 0; d < DM; d++) s = fmaf(wp[d], ps[d], s);
    Wout[(size_t)nn * DM + k] = s;

    if (k == 0) {
        float sb = 0.f;
        const float* bp = b + h * DM;
        for (int d = 0; d < DM; d++) sb = fmaf(bp[d], ps[d], sb);
        bout[nn] = sb;
    }
}

// ---------------------------------------------------------------------------
// Replicated-bias builder: BR[v][r][c] = bias_v[c] for r in 0..15
//   v: 0 b_in, 1 b_he, 2+l bqk (240, zero-padded), 5+l bo
// ---------------------------------------------------------------------------
__global__ void bias_rep_kernel(const float* __restrict__ b_in,
                                const float* __restrict__ b_he,
                                const float* __restrict__ WT,
                                const float* __restrict__ bo,
                                float* __restrict__ BR)
{
    const int v = blockIdx.x;        // 0..7
    const int c = threadIdx.x;       // 0..255
    float val = 0.f;
    if (v == 0)      val = b_in[c];
    else if (v == 1) val = b_he[c];
    else if (v < 5)  { const int l = v - 2; if (c < NQK) val = WT[BQK(l) + c]; }
    else             { const int l = v - 5; val = bo[l * 256 + c]; }
#pragma unroll
    for (int r = 0; r < 16; r++)
        BR[(size_t)(v * 16 + r) * 256 + c] = val;
}

// ---------------------------------------------------------------------------
// LayerNorm + ELU
// ---------------------------------------------------------------------------
__global__ void ln_elu_kernel(const float* __restrict__ h,
                              const float* __restrict__ gamma,
                              const float* __restrict__ beta,
                              float* __restrict__ z)
{
    const int gw   = blockIdx.x * (blockDim.x >> 5) + (threadIdx.x >> 5);
    const int lane = threadIdx.x & 31;
    if (gw >= NTOT) return;

    const float4* hp = (const float4*)(h + (size_t)gw * DM);
    float4 v0 = hp[lane * 2];
    float4 v1 = hp[lane * 2 + 1];
    float vv[8] = {v0.x, v0.y, v0.z, v0.w, v1.x, v1.y, v1.z, v1.w};

    float s = 0.f;
#pragma unroll
    for (int i = 0; i < 8; i++) s += vv[i];
#pragma unroll
    for (int o = 16; o; o >>= 1) s += __shfl_xor_sync(0xffffffffu, s, o);
    const float mean = s * (1.0f / DM);

    float sq = 0.f;
#pragma unroll
    for (int i = 0; i < 8; i++) { float d = vv[i] - mean; sq = fmaf(d, d, sq); }
#pragma unroll
    for (int o = 16; o; o >>= 1) sq += __shfl_xor_sync(0xffffffffu, sq, o);
    const float inv = rsqrtf(sq * (1.0f / DM) + 1e-5f);

    const int c = lane * 8;
    float out[8];
#pragma unroll
    for (int i = 0; i < 8; i++) {
        float t = (vv[i] - mean) * inv * gamma[c + i] + beta[c + i];
        out[i] = (t > 0.f) ? t : expm1f(t);
    }
    float4* zp = (float4*)(z + (size_t)gw * DM);
    zp[lane * 2]     = make_float4(out[0], out[1], out[2], out[3]);
    zp[lane * 2 + 1] = make_float4(out[4], out[5], out[6], out[7]);
}

// ---------------------------------------------------------------------------
// Zero S / Ksum accumulators
// ---------------------------------------------------------------------------
__global__ void zero_s_kernel()
{
    const int i = blockIdx.x * blockDim.x + threadIdx.x;
    if (i < NF * DM) g_S[i] = 0.f;
    if (i < NF)      g_Ks[i] = 0.f;
}

// ---------------------------------------------------------------------------
// S[hm, k] = sum_n Kp[n, hm] * z[n, k] ; Ksum = sum_n Kp
//   (Kp = QKp + NF, row stride NQKP). blockIdx = (n-chunk, head), 256 threads.
// ---------------------------------------------------------------------------
__global__ __launch_bounds__(256)
void s_kernel(const float* __restrict__ Kp, const float* __restrict__ z)
{
    __shared__ float kpS[128][31];
    const int h   = blockIdx.y;
    const int n0  = blockIdx.x * 128;
    const int tid = threadIdx.x;
    const int rows = min(128, NTOT - n0);

    for (int i = tid; i < rows * MF; i += 256) {
        const int r = i / MF, m = i % MF;
        kpS[r][m] = Kp[(size_t)(n0 + r) * NQKP + h * MF + m];
    }
    __syncthreads();

    float acc[MF];
#pragma unroll
    for (int m = 0; m < MF; m++) acc[m] = 0.f;

    for (int r = 0; r < rows; r++) {
        const float v = z[(size_t)(n0 + r) * DM + tid];
#pragma unroll
        for (int m = 0; m < MF; m++)
            acc[m] = fmaf(kpS[r][m], v, acc[m]);
    }
#pragma unroll
    for (int m = 0; m < MF; m++)
        atomicAdd(&g_S[(size_t)(h * MF + m) * DM + tid], acc[m]);

    if (tid < MF) {
        float s = 0.f;
        for (int r = 0; r < rows; r++) s += kpS[r][tid];
        atomicAdd(&g_Ks[h * MF + tid], s);
    }
}

// ---------------------------------------------------------------------------
// KV[hm, d] = sum_k S[hm, k] * Wv[k, h*256+d] + Ks[hm] * bv[h*256+d]
// ---------------------------------------------------------------------------
__global__ __launch_bounds__(256)
void kv2_kernel(const float* __restrict__ Wv, const float* __restrict__ bv)
{
    __shared__ float srow[DM];
    const int hm = blockIdx.x;       // 0..119
    const int h  = hm / MF;
    const int d  = threadIdx.x;      // 0..255
    srow[d] = g_S[(size_t)hm * DM + d];
    __syncthreads();

    float acc = 0.f;
    const float* wp = Wv + h * DM + d;
#pragma unroll 8
    for (int k = 0; k < DM; k++)
        acc = fmaf(srow[k], wp[(size_t)k * (HEADS * DM)], acc);
    g_KV[(size_t)hm * DM + d] = acc + g_Ks[hm] * bv[h * DM + d];
}

// ---------------------------------------------------------------------------
// W2t[j, hm] = sum_d KV[hm, d] * Wo[h*256+d, j]   (K-major [256 x 120])
// ---------------------------------------------------------------------------
__global__ __launch_bounds__(256)
void w2_kernel(const float* __restrict__ Wo)
{
    __shared__ float kvrow[DM];
    const int hm = blockIdx.x;       // 0..119
    const int h  = hm / MF;
    const int j  = threadIdx.x;      // 0..255
    kvrow[j] = g_KV[(size_t)hm * DM + j];
    __syncthreads();

    float acc = 0.f;
    const float* wp = Wo + (size_t)(h * DM) * DM + j;
#pragma unroll 8
    for (int d = 0; d < DM; d++)
        acc = fmaf(kvrow[d], wp[(size_t)d * DM], acc);
    g_W2t[(size_t)j * NF + hm] = acc;
}

// ---------------------------------------------------------------------------
// Qps[n, hm] = Qp[n, hm] / (sum_m Qp[n, h*MF+m] * Ks[h*MF+m] + 1e-6)
// ---------------------------------------------------------------------------
__global__ __launch_bounds__(256)
void qps_kernel(const float* __restrict__ QKp, float* __restrict__ Qps)
{
    __shared__ float ks[NF];
    const int tid = threadIdx.x;
    if (tid < NF) ks[tid] = g_Ks[tid];
    __syncthreads();

    const int n = blockIdx.x * 256 + tid;
    if (n >= NTOT) return;
    const float* q = QKp + (size_t)n * NQKP;
    float* o = Qps + (size_t)n * NF;

#pragma unroll
    for (int h = 0; h < HEADS; h++) {
        float den = 0.f;
#pragma unroll
        for (int m = 0; m < MF; m++)
            den = fmaf(q[h * MF + m], ks[h * MF + m], den);
        const float inv = 1.0f / (den + 1e-6f);
#pragma unroll
        for (int m = 0; m < MF; m++)
            o[h * MF + m] = q[h * MF + m] * inv;
    }
}

// ---------------------------------------------------------------------------
// Launch
// ---------------------------------------------------------------------------
extern "C" void kernel_launch(void* const* d_in, const int* in_sizes, int n_in,
                              void* d_out, int out_size)
{
    const float* x    = (const float*)d_in[0];
    const float* H    = (const float*)d_in[1];
    const float* proj = (const float*)d_in[2];
    const float* W_in = (const float*)d_in[3];
    const float* b_in = (const float*)d_in[4];
    const float* W_he = (const float*)d_in[5];
    const float* b_he = (const float*)d_in[6];
    const float* ln_g = (const float*)d_in[7];
    const float* ln_b = (const float*)d_in[8];
    const float* Wq   = (const float*)d_in[9];
    const float* bq   = (const float*)d_in[10];
    const float* Wk   = (const float*)d_in[11];
    const float* bk   = (const float*)d_in[12];
    const float* Wv   = (const float*)d_in[13];
    const float* bv   = (const float*)d_in[14];
    const float* Wo   = (const float*)d_in[15];
    const float* bo   = (const float*)d_in[16];

    float* h = (float*)d_out;

    cudaFuncSetAttribute(gemm_tc, cudaFuncAttributeMaxDynamicSharedMemorySize,
                         GEMM_SMEM);

    float *z, *QKp, *Qps, *W2t, *WT, *BR;
    cudaGetSymbolAddress((void**)&z,   g_z);
    cudaGetSymbolAddress((void**)&QKp, g_QKp);
    cudaGetSymbolAddress((void**)&Qps, g_Qps);
    cudaGetSymbolAddress((void**)&W2t, g_W2t);
    cudaGetSymbolAddress((void**)&WT,  g_WT);
    cudaGetSymbolAddress((void**)&BR,  g_BR);

    // weight prep: 3 launches
    mega_transpose<<<dim3(32, 8, 2), dim3(32, 8)>>>(W_in, W_he, WT);
    mega_fold<<<dim3(NF, 2, LNUM), 256>>>(Wq, bq, Wk, bk, proj, WT);
    bias_rep_kernel<<<8, 256>>>(b_in, b_he, WT, bo, BR);

    const int MB = (NTOT + 127) / 128;
    const dim3 g256(2, MB);      // two 128-col tiles
    const dim3 gHead(MB, HEADS);

    // h = x @ W_in + b_in ; h += H @ W_he + b_he
    gemm_tc<<<g256, 256, GEMM_SMEM>>>(x, WT + WT_IN, h, BR + BR_V(0), NTOT, 256, 256, 256, 0);
    gemm_tc<<<g256, 256, GEMM_SMEM>>>(H, WT + WT_HE, h, BR + BR_V(1), NTOT, 256, EDIM, 256, 1);

    for (int l = 0; l < LNUM; l++) {
        ln_elu_kernel<<<(NTOT + 7) / 8, 256>>>(h, ln_g + l * DM, ln_b + l * DM, z);

        // [Qp | Kp] = exp(z @ Wqk' + bqk') + 1e-6   (N=240, padded stores to 256)
        gemm_tc<<<g256, 256, GEMM_SMEM>>>(z, WT + WQK(l), QKp, BR + BR_V(2 + l),
                                          NTOT, NQK, 256, NQKP, 2);

        // S = Kp^T @ z ; Ksum = sum Kp
        zero_s_kernel<<<(NF * DM + 255) / 256, 256>>>();
        s_kernel<<<gHead, 256>>>(QKp + NF, z);

        // KV = S @ Wv + Ks (x) bv ;  W2t = (KV @ Wo)^T
        kv2_kernel<<<NF, 256>>>(Wv + (size_t)l * DM * HEADS * DM,
                                bv + (size_t)l * (HEADS * DM));
        w2_kernel<<<NF, 256>>>(Wo + (size_t)l * (HEADS * DM) * DM);

        // Qps = Qp / (Qp . Ksum + 1e-6)
        qps_kernel<<<(NTOT + 255) / 256, 256>>>(QKp, Qps);

        // h += Qps @ W2t^T + bo    (M=50000, N=256, K=120)
        gemm_tc<<<g256, 256, GEMM_SMEM>>>(Qps, W2t, h, BR + BR_V(5 + l),
                                          NTOT, 256, NF, 256, 1);
    }
}

// round 17
// speedup vs baseline: 1.3778x; 1.3778x over previous
#include <cuda_runtime.h>
#include <cuda_fp16.h>
#include <math.h>
#include <stdint.h>
#include <mma.h>

using namespace nvcuda;

// Problem constants
#define NTOT 50000
#define EDIM 1000
#define DIN  256
#define DM   256
#define HEADS 4
#define MF   30
#define LNUM 3
#define NF   (HEADS * MF)          // 120 feature columns
#define NQK  (2 * NF)              // 240 logical [Qp | Kp] columns
#define NQKP 256                   // padded row stride of QKp
#define QPS_SCALE   4096.0f        // 2^12: lifts Qps out of fp16 subnormal range
#define QPS_ISCALE  (1.0f / 4096.0f)

// ---------------------------------------------------------------------------
// Scratch (device globals — no allocations allowed)
// ---------------------------------------------------------------------------
__device__ float  g_z   [NTOT * DM];        // ln output (fp32, for s_kernel)
__device__ __half g_zh  [NTOT * DM];        // ln output (fp16, for QK gemm)
__device__ __half g_xh  [NTOT * DIN];       // x in fp16
__device__ __half g_Hh  [NTOT * EDIM];      // H in fp16
__device__ float  g_QKp [NTOT * NQKP];      // [Qp | Kp | pad] features (fp32)
__device__ __half g_Qpsh[NTOT * NF];        // (Qp / den) * 2^12 (fp16)
__device__ float  g_S   [NF * DM];          // Kp^T @ z
__device__ float  g_Ks  [NF];               // sum_n Kp
__device__ float  g_KV  [NF * DM];          // S @ Wv + Ks (x) bv
__device__ __half g_W2th[DM * NF];          // (KV @ Wo)^T * 2^-12  [256 x 120] fp16
__device__ float  g_BR  [8 * 16 * 256];     // 16-row replicated biases (fp32)
__device__ float  g_BQK [LNUM * NQK];       // folded QK biases
// fp16 transposed / folded weights
__device__ __half g_WTh[505856];

#define WH_IN   0
#define WH_HE   65536
#define WHQK(l) (321536 + (l) * 61440)      // 240 rows x 256 (rows 0-119 Q, 120-239 K)
#define BR_V(v) ((v) * 16 * 256)            // 0 b_in, 1 b_he, 2+l bqk, 5+l bo

// ---------------------------------------------------------------------------
// cp.async helpers (base ISA, sm_80+)
// ---------------------------------------------------------------------------
__device__ __forceinline__ uint32_t smem_u32(const void* p) {
    uint32_t a;
    asm("{ .reg .u64 t; cvta.to.shared.u64 t, %1; cvt.u32.u64 %0, t; }"
        : "=r"(a) : "l"(p));
    return a;
}

__device__ __forceinline__ void cpasync16(uint32_t dst, const void* src, int srcsize) {
    asm volatile("cp.async.cg.shared.global [%0], [%1], 16, %2;"
        :: "r"(dst), "l"(src), "r"(srcsize) : "memory");
}
#define CP_COMMIT() asm volatile("cp.async.commit_group;" ::: "memory")
#define CP_WAIT2()  asm volatile("cp.async.wait_group 2;" ::: "memory")

// ---------------------------------------------------------------------------
// WMMA FP16 GEMM: C[M x Nn] = A[M x K] @ Bt^T + bias (+C) (or exp epilogue)
//   A  : [M, K]  row-major __half (row stride == K)
//   Bt : [Nn, K] row-major __half (K-major == wmma col_major B)
//   biasRep : 16-row replicated fp32 bias [16 x 256]
//   Block tile 128 x 128, BK = 32, 8 warps (warp tile 64 x 32), 3-stage pipe.
//   C written 128 cols wide (buffers padded so Cstride covers col0+128).
//   mode: 0 = C = v + bias ; 1 = C += v + bias ; 2 = C = exp(v + bias) + 1e-6
// ---------------------------------------------------------------------------
#define BK 32
#define ROWH 40                              // padded row pitch in halves (80 B)
#define STAGE_H (2 * 128 * ROWH)             // 10240 halves = 20480 B per stage
#define GEMM_SMEM 67584                      // max(3*20480, tail 128*132*4)

__global__ __launch_bounds__(256, 2)
void gemm_tc(const __half* __restrict__ A, const __half* __restrict__ Bt,
             float* __restrict__ C, const float* __restrict__ biasRep,
             int M, int Nn, int K, int Cstride, int mode)
{
    extern __shared__ __align__(16) char smem_raw[];
    __half* smem = (__half*)smem_raw;

    const int tid  = threadIdx.x;
    const int wid  = tid >> 5;
    const int wm   = wid & 1;          // 0..1 -> 64-row slab
    const int wn   = wid >> 1;         // 0..3 -> 32-col slab
    const int row0 = blockIdx.y * 128;
    const int col0 = blockIdx.x * 128;

    const int T = (K + BK - 1) / BK;

    wmma::fragment<wmma::accumulator, 16, 16, 16, float> acc[4][2];
#pragma unroll
    for (int i = 0; i < 4; i++)
#pragma unroll
        for (int j = 0; j < 2; j++) wmma::fill_fragment(acc[i][j], 0.f);

    auto load_tile = [&](int tt, int ss) {
        __half* As = smem + ss * STAGE_H;
        __half* Bs = As + 128 * ROWH;
        const uint32_t asb = smem_u32(As);
        const uint32_t bsb = smem_u32(Bs);
        const int kbase = tt * BK;
#pragma unroll
        for (int i = 0; i < 2; i++) {          // A: 512 16B chunks (8 halves each)
            const int id  = tid + i * 256;
            const int row = id >> 2, c = id & 3;
            const int gr = row0 + row;
            const int gk = kbase + c * 8;
            const int ok = (gr < M) && (gk + 8 <= K);
            const __half* src = ok ? (A + (size_t)gr * K + gk) : A;
            cpasync16(asb + (row * ROWH + c * 8) * 2, src, ok ? 16 : 0);
        }
#pragma unroll
        for (int i = 0; i < 2; i++) {          // B: 512 16B chunks
            const int id  = tid + i * 256;
            const int row = id >> 2, c = id & 3;
            const int gn = col0 + row;
            const int gk = kbase + c * 8;
            const int ok = (gn < Nn) && (gk + 8 <= K);
            const __half* src = ok ? (Bt + (size_t)gn * K + gk) : Bt;
            cpasync16(bsb + (row * ROWH + c * 8) * 2, src, ok ? 16 : 0);
        }
    };

    // 3-stage prologue
    load_tile(0, 0);
    CP_COMMIT();
    if (T > 1) load_tile(1, 1);
    CP_COMMIT();

    for (int t = 0; t < T; t++) {
        if (t + 2 < T) load_tile(t + 2, (t + 2) % 3);
        CP_COMMIT();
        CP_WAIT2();
        __syncthreads();

        const __half* As = smem + (t % 3) * STAGE_H;
        const __half* Bs = As + 128 * ROWH;

#pragma unroll
        for (int ks = 0; ks < 2; ks++) {
            const int k0 = ks * 16;
            wmma::fragment<wmma::matrix_a, 16, 16, 16, __half, wmma::row_major> af[4];
            wmma::fragment<wmma::matrix_b, 16, 16, 16, __half, wmma::col_major> bf[2];
#pragma unroll
            for (int i = 0; i < 4; i++)
                wmma::load_matrix_sync(af[i], As + (wm * 64 + i * 16) * ROWH + k0, ROWH);
#pragma unroll
            for (int j = 0; j < 2; j++)
                wmma::load_matrix_sync(bf[j], Bs + (wn * 32 + j * 16) * ROWH + k0, ROWH);
#pragma unroll
            for (int i = 0; i < 4; i++)
#pragma unroll
                for (int j = 0; j < 2; j++)
                    wmma::mma_sync(acc[i][j], af[i], bf[j], acc[i][j]);
        }
        __syncthreads();
    }

    // ---- epilogue ----
    const bool tail = (row0 + 128 > M);
    if (!tail) {
        // direct fragment path: bias via accumulator-layout fragment
        wmma::fragment<wmma::accumulator, 16, 16, 16, float> bfr[2];
#pragma unroll
        for (int j = 0; j < 2; j++)
            wmma::load_matrix_sync(bfr[j], biasRep + col0 + wn * 32 + j * 16, 256,
                                   wmma::mem_row_major);
#pragma unroll
        for (int i = 0; i < 4; i++) {
            const int gr0 = row0 + wm * 64 + i * 16;
#pragma unroll
            for (int j = 0; j < 2; j++) {
                const int gc0 = col0 + wn * 32 + j * 16;
                float* cp = C + (size_t)gr0 * Cstride + gc0;
                if (mode == 1) {
                    wmma::fragment<wmma::accumulator, 16, 16, 16, float> cf;
                    wmma::load_matrix_sync(cf, cp, Cstride, wmma::mem_row_major);
#pragma unroll
                    for (int e = 0; e < cf.num_elements; e++)
                        acc[i][j].x[e] += bfr[j].x[e] + cf.x[e];
                } else if (mode == 2) {
#pragma unroll
                    for (int e = 0; e < bfr[j].num_elements; e++)
                        acc[i][j].x[e] = __expf(acc[i][j].x[e] + bfr[j].x[e]) + 1e-6f;
                } else {
#pragma unroll
                    for (int e = 0; e < bfr[j].num_elements; e++)
                        acc[i][j].x[e] += bfr[j].x[e];
                }
                wmma::store_matrix_sync(cp, acc[i][j], Cstride, wmma::mem_row_major);
            }
        }
    } else {
        // staged fallback for the M-tail block (reuses stage smem as fp32)
        float* Cs = (float*)smem_raw;          // 128 x 132
        __syncthreads();
#pragma unroll
        for (int i = 0; i < 4; i++)
#pragma unroll
            for (int j = 0; j < 2; j++)
                wmma::store_matrix_sync(Cs + (wm * 64 + i * 16) * 132 + wn * 32 + j * 16,
                                        acc[i][j], 132, wmma::mem_row_major);
        __syncthreads();

        const int r    = tid >> 1;
        const int half = tid & 1;
        const int gr   = row0 + r;
        if (gr < M) {
            const float* sp = Cs + r * 132 + half * 64;
#pragma unroll
            for (int j = 0; j < 16; j++) {
                const int cc = col0 + half * 64 + j * 4;
                float4 v = *(const float4*)(sp + j * 4);
                float4 bv = *(const float4*)(biasRep + cc);
                v.x += bv.x; v.y += bv.y; v.z += bv.z; v.w += bv.w;
                float* cp = C + (size_t)gr * Cstride + cc;
                if (mode == 1) {
                    float4 o = *(float4*)cp;
                    v.x += o.x; v.y += o.y; v.z += o.z; v.w += o.w;
                } else if (mode == 2) {
                    v.x = __expf(v.x) + 1e-6f; v.y = __expf(v.y) + 1e-6f;
                    v.z = __expf(v.z) + 1e-6f; v.w = __expf(v.w) + 1e-6f;
                }
                *(float4*)cp = v;
            }
        }
    }
}

// ---------------------------------------------------------------------------
// fp32 -> fp16 conversion (vectorized), n % 4 == 0
// ---------------------------------------------------------------------------
__global__ void tohalf_kernel(const float* __restrict__ src, __half* __restrict__ dst,
                              int n4)
{
    const int i = blockIdx.x * blockDim.x + threadIdx.x;
    if (i >= n4) return;
    float4 v = ((const float4*)src)[i];
    __half2* d = (__half2*)dst;
    d[2 * i]     = __floats2half2_rn(v.x, v.y);
    d[2 * i + 1] = __floats2half2_rn(v.z, v.w);
}

// ---------------------------------------------------------------------------
// Mega-transpose (W_in, W_he) -> fp16 K-major
// ---------------------------------------------------------------------------
__global__ void mega_transpose(const float* __restrict__ W_in,
                               const float* __restrict__ W_he,
                               __half* __restrict__ WTh)
{
    const int z = blockIdx.z;
    const float* src; __half* dst; int K, Nn;
    if (z == 0) { src = W_in; dst = WTh + WH_IN; K = 256;  Nn = 256; }
    else        { src = W_he; dst = WTh + WH_HE; K = EDIM; Nn = 256; }

    const int k0 = blockIdx.x * 32, n0 = blockIdx.y * 32;
    if (k0 >= K || n0 >= Nn) return;

    __shared__ float tile[32][33];
    const int tx = threadIdx.x, ty = threadIdx.y;
#pragma unroll
    for (int r = 0; r < 4; r++) {
        const int k = k0 + ty + r * 8;
        if (k < K && n0 + tx < Nn) tile[ty + r * 8][tx] = src[(size_t)k * Nn + n0 + tx];
    }
    __syncthreads();
#pragma unroll
    for (int r = 0; r < 4; r++) {
        const int n = n0 + ty + r * 8;
        if (n < Nn && k0 + tx < K)
            dst[(size_t)n * K + k0 + tx] = __float2half(tile[tx][ty + r * 8]);
    }
}

// ---------------------------------------------------------------------------
// Mega-fold: FAVOR+ weight folds -> fp16, grid (NF, 2, LNUM)
// ---------------------------------------------------------------------------
__global__ __launch_bounds__(256)
void mega_fold(const float* __restrict__ Wq, const float* __restrict__ bq,
               const float* __restrict__ Wk, const float* __restrict__ bk,
               const float* __restrict__ proj, __half* __restrict__ WTh,
               float* __restrict__ BQK)
{
    __shared__ float ps[DM];
    const int l   = blockIdx.z;
    const int isK = blockIdx.y;
    const float* W = (isK ? Wk : Wq) + (size_t)l * DM * HEADS * DM;
    const float* b = (isK ? bk : bq) + (size_t)l * (HEADS * DM);
    __half* Wout = WTh + WHQK(l) + isK * (NF * DM);
    float* bout  = BQK + l * NQK + isK * NF;

    const int nn = blockIdx.x;       // 0..119
    const int h = nn / MF, m = nn % MF;
    const int k = threadIdx.x;       // 0..255
    const float c = 0.25f * 0.18257418583505536f;
    ps[k] = c * proj[(size_t)m * DM + k];
    __syncthreads();

    float s = 0.f;
    const float* wp = W + (size_t)k * (HEADS * DM) + h * DM;
#pragma unroll 8
    for (int d = 0; d < DM; d++) s = fmaf(wp[d], ps[d], s);
    Wout[(size_t)nn * DM + k] = __float2half(s);

    if (k == 0) {
        float sb = 0.f;
        const float* bp = b + h * DM;
        for (int d = 0; d < DM; d++) sb = fmaf(bp[d], ps[d], sb);
        bout[nn] = sb;
    }
}

// ---------------------------------------------------------------------------
// Replicated-bias builder: BR[v][r][c] = bias_v[c] for r in 0..15
// ---------------------------------------------------------------------------
__global__ void bias_rep_kernel(const float* __restrict__ b_in,
                                const float* __restrict__ b_he,
                                const float* __restrict__ BQK,
                                const float* __restrict__ bo,
                                float* __restrict__ BR)
{
    const int v = blockIdx.x;        // 0..7
    const int c = threadIdx.x;       // 0..255
    float val = 0.f;
    if (v == 0)      val = b_in[c];
    else if (v == 1) val = b_he[c];
    else if (v < 5)  { const int l = v - 2; if (c < NQK) val = BQK[l * NQK + c]; }
    else             { const int l = v - 5; val = bo[l * 256 + c]; }
#pragma unroll
    for (int r = 0; r < 16; r++)
        BR[(size_t)(v * 16 + r) * 256 + c] = val;
}

// ---------------------------------------------------------------------------
// LayerNorm + ELU; writes fp32 z (for s_kernel) and fp16 z_h (for QK gemm)
// ---------------------------------------------------------------------------
__global__ void ln_elu_kernel(const float* __restrict__ h,
                              const float* __restrict__ gamma,
                              const float* __restrict__ beta,
                              float* __restrict__ z, __half* __restrict__ zh)
{
    const int gw   = blockIdx.x * (blockDim.x >> 5) + (threadIdx.x >> 5);
    const int lane = threadIdx.x & 31;
    if (gw >= NTOT) return;

    const float4* hp = (const float4*)(h + (size_t)gw * DM);
    float4 v0 = hp[lane * 2];
    float4 v1 = hp[lane * 2 + 1];
    float vv[8] = {v0.x, v0.y, v0.z, v0.w, v1.x, v1.y, v1.z, v1.w};

    float s = 0.f;
#pragma unroll
    for (int i = 0; i < 8; i++) s += vv[i];
#pragma unroll
    for (int o = 16; o; o >>= 1) s += __shfl_xor_sync(0xffffffffu, s, o);
    const float mean = s * (1.0f / DM);

    float sq = 0.f;
#pragma unroll
    for (int i = 0; i < 8; i++) { float d = vv[i] - mean; sq = fmaf(d, d, sq); }
#pragma unroll
    for (int o = 16; o; o >>= 1) sq += __shfl_xor_sync(0xffffffffu, sq, o);
    const float inv = rsqrtf(sq * (1.0f / DM) + 1e-5f);

    const int c = lane * 8;
    float out[8];
#pragma unroll
    for (int i = 0; i < 8; i++) {
        float t = (vv[i] - mean) * inv * gamma[c + i] + beta[c + i];
        out[i] = (t > 0.f) ? t : expm1f(t);
    }
    float4* zp = (float4*)(z + (size_t)gw * DM);
    zp[lane * 2]     = make_float4(out[0], out[1], out[2], out[3]);
    zp[lane * 2 + 1] = make_float4(out[4], out[5], out[6], out[7]);

    __half2* zhp = (__half2*)(zh + (size_t)gw * DM);
#pragma unroll
    for (int i = 0; i < 4; i++)
        zhp[lane * 4 + i] = __floats2half2_rn(out[2 * i], out[2 * i + 1]);
}

// ---------------------------------------------------------------------------
// Zero S / Ksum accumulators
// ---------------------------------------------------------------------------
__global__ void zero_s_kernel()
{
    const int i = blockIdx.x * blockDim.x + threadIdx.x;
    if (i < NF * DM) g_S[i] = 0.f;
    if (i < NF)      g_Ks[i] = 0.f;
}

// ---------------------------------------------------------------------------
// S[hm, k] = sum_n Kp[n, hm] * z[n, k] ; Ksum = sum_n Kp
//   (Kp = QKp + NF, row stride NQKP). blockIdx = (n-chunk, head), 256 threads.
// ---------------------------------------------------------------------------
__global__ __launch_bounds__(256)
void s_kernel(const float* __restrict__ Kp, const float* __restrict__ z)
{
    __shared__ float kpS[128][31];
    const int h   = blockIdx.y;
    const int n0  = blockIdx.x * 128;
    const int tid = threadIdx.x;
    const int rows = min(128, NTOT - n0);

    for (int i = tid; i < rows * MF; i += 256) {
        const int r = i / MF, m = i % MF;
        kpS[r][m] = Kp[(size_t)(n0 + r) * NQKP + h * MF + m];
    }
    __syncthreads();

    float acc[MF];
#pragma unroll
    for (int m = 0; m < MF; m++) acc[m] = 0.f;

    for (int r = 0; r < rows; r++) {
        const float v = z[(size_t)(n0 + r) * DM + tid];
#pragma unroll
        for (int m = 0; m < MF; m++)
            acc[m] = fmaf(kpS[r][m], v, acc[m]);
    }
#pragma unroll
    for (int m = 0; m < MF; m++)
        atomicAdd(&g_S[(size_t)(h * MF + m) * DM + tid], acc[m]);

    if (tid < MF) {
        float s = 0.f;
        for (int r = 0; r < rows; r++) s += kpS[r][tid];
        atomicAdd(&g_Ks[h * MF + tid], s);
    }
}

// ---------------------------------------------------------------------------
// KV[hm, d] = sum_k S[hm, k] * Wv[k, h*256+d] + Ks[hm] * bv[h*256+d]
// ---------------------------------------------------------------------------
__global__ __launch_bounds__(256)
void kv2_kernel(const float* __restrict__ Wv, const float* __restrict__ bv)
{
    __shared__ float srow[DM];
    const int hm = blockIdx.x;       // 0..119
    const int h  = hm / MF;
    const int d  = threadIdx.x;      // 0..255
    srow[d] = g_S[(size_t)hm * DM + d];
    __syncthreads();

    float acc = 0.f;
    const float* wp = Wv + h * DM + d;
#pragma unroll 8
    for (int k = 0; k < DM; k++)
        acc = fmaf(srow[k], wp[(size_t)k * (HEADS * DM)], acc);
    g_KV[(size_t)hm * DM + d] = acc + g_Ks[hm] * bv[h * DM + d];
}

// ---------------------------------------------------------------------------
// W2t[j, hm] = (sum_d KV[hm, d] * Wo[h*256+d, j]) * 2^-12  (fp16 [256 x 120])
// ---------------------------------------------------------------------------
__global__ __launch_bounds__(256)
void w2_kernel(const float* __restrict__ Wo)
{
    __shared__ float kvrow[DM];
    const int hm = blockIdx.x;       // 0..119
    const int h  = hm / MF;
    const int j  = threadIdx.x;      // 0..255
    kvrow[j] = g_KV[(size_t)hm * DM + j];
    __syncthreads();

    float acc = 0.f;
    const float* wp = Wo + (size_t)(h * DM) * DM + j;
#pragma unroll 8
    for (int d = 0; d < DM; d++)
        acc = fmaf(kvrow[d], wp[(size_t)d * DM], acc);
    g_W2th[(size_t)j * NF + hm] = __float2half(acc * QPS_ISCALE);
}

// ---------------------------------------------------------------------------
// Qps[n, hm] = Qp[n, hm] / (dot(Qp[n, h], Ks[h]) + 1e-6) * 2^12 -> fp16
//   (2^12 lift keeps values in fp16 normal range; exactly undone by W2t*2^-12)
// ---------------------------------------------------------------------------
__global__ __launch_bounds__(256)
void qps_kernel(const float* __restrict__ QKp, __half* __restrict__ Qpsh)
{
    __shared__ float ks[NF];
    const int tid = threadIdx.x;
    if (tid < NF) ks[tid] = g_Ks[tid];
    __syncthreads();

    const int n = blockIdx.x * 256 + tid;
    if (n >= NTOT) return;
    const float* q = QKp + (size_t)n * NQKP;
    __half* o = Qpsh + (size_t)n * NF;

#pragma unroll
    for (int h = 0; h < HEADS; h++) {
        float den = 0.f;
#pragma unroll
        for (int m = 0; m < MF; m++)
            den = fmaf(q[h * MF + m], ks[h * MF + m], den);
        const float inv = QPS_SCALE / (den + 1e-6f);
#pragma unroll
        for (int m = 0; m < MF; m++)
            o[h * MF + m] = __float2half(q[h * MF + m] * inv);
    }
}

// ---------------------------------------------------------------------------
// Launch
// ---------------------------------------------------------------------------
extern "C" void kernel_launch(void* const* d_in, const int* in_sizes, int n_in,
                              void* d_out, int out_size)
{
    const float* x    = (const float*)d_in[0];
    const float* H    = (const float*)d_in[1];
    const float* proj = (const float*)d_in[2];
    const float* W_in = (const float*)d_in[3];
    const float* b_in = (const float*)d_in[4];
    const float* W_he = (const float*)d_in[5];
    const float* b_he = (const float*)d_in[6];
    const float* ln_g = (const float*)d_in[7];
    const float* ln_b = (const float*)d_in[8];
    const float* Wq   = (const float*)d_in[9];
    const float* bq   = (const float*)d_in[10];
    const float* Wk   = (const float*)d_in[11];
    const float* bk   = (const float*)d_in[12];
    const float* Wv   = (const float*)d_in[13];
    const float* bv   = (const float*)d_in[14];
    const float* Wo   = (const float*)d_in[15];
    const float* bo   = (const float*)d_in[16];

    float* h = (float*)d_out;

    cudaFuncSetAttribute(gemm_tc, cudaFuncAttributeMaxDynamicSharedMemorySize,
                         GEMM_SMEM);

    float  *z, *QKp, *BR, *BQK;
    __half *zh, *xh, *Hh, *Qpsh, *W2th, *WTh;
    cudaGetSymbolAddress((void**)&z,    g_z);
    cudaGetSymbolAddress((void**)&zh,   g_zh);
    cudaGetSymbolAddress((void**)&xh,   g_xh);
    cudaGetSymbolAddress((void**)&Hh,   g_Hh);
    cudaGetSymbolAddress((void**)&QKp,  g_QKp);
    cudaGetSymbolAddress((void**)&Qpsh, g_Qpsh);
    cudaGetSymbolAddress((void**)&W2th, g_W2th);
    cudaGetSymbolAddress((void**)&WTh,  g_WTh);
    cudaGetSymbolAddress((void**)&BR,   g_BR);
    cudaGetSymbolAddress((void**)&BQK,  g_BQK);

    // input + weight prep
    tohalf_kernel<<<(NTOT * DIN / 4 + 255) / 256, 256>>>(x, xh, NTOT * DIN / 4);
    tohalf_kernel<<<(NTOT * EDIM / 4 + 255) / 256, 256>>>(H, Hh, NTOT * EDIM / 4);
    mega_transpose<<<dim3(32, 8, 2), dim3(32, 8)>>>(W_in, W_he, WTh);
    mega_fold<<<dim3(NF, 2, LNUM), 256>>>(Wq, bq, Wk, bk, proj, WTh, BQK);
    bias_rep_kernel<<<8, 256>>>(b_in, b_he, BQK, bo, BR);

    const int MB = (NTOT + 127) / 128;
    const dim3 g256(2, MB);      // two 128-col tiles
    const dim3 gHead(MB, HEADS);

    // h = x @ W_in + b_in ; h += H @ W_he + b_he
    gemm_tc<<<g256, 256, GEMM_SMEM>>>(xh, WTh + WH_IN, h, BR + BR_V(0), NTOT, 256, DIN, 256, 0);
    gemm_tc<<<g256, 256, GEMM_SMEM>>>(Hh, WTh + WH_HE, h, BR + BR_V(1), NTOT, 256, EDIM, 256, 1);

    for (int l = 0; l < LNUM; l++) {
        ln_elu_kernel<<<(NTOT + 7) / 8, 256>>>(h, ln_g + l * DM, ln_b + l * DM, z, zh);

        // [Qp | Kp] = exp(z @ Wqk' + bqk') + 1e-6   (N=240, padded stores to 256)
        gemm_tc<<<g256, 256, GEMM_SMEM>>>(zh, WTh + WHQK(l), QKp, BR + BR_V(2 + l),
                                          NTOT, NQK, DM, NQKP, 2);

        // S = Kp^T @ z ; Ksum = sum Kp
        zero_s_kernel<<<(NF * DM + 255) / 256, 256>>>();
        s_kernel<<<gHead, 256>>>(QKp + NF, z);

        // KV = S @ Wv + Ks (x) bv ;  W2t = (KV @ Wo)^T * 2^-12 (fp16)
        kv2_kernel<<<NF, 256>>>(Wv + (size_t)l * DM * HEADS * DM,
                                bv + (size_t)l * (HEADS * DM));
        w2_kernel<<<NF, 256>>>(Wo + (size_t)l * (HEADS * DM) * DM);

        // Qps = Qp / den * 2^12  (fp16)
        qps_kernel<<<(NTOT + 255) / 256, 256>>>(QKp, Qpsh);

        // h += Qps @ W2t^T + bo    (M=50000, N=256, K=120)
        gemm_tc<<<g256, 256, GEMM_SMEM>>>(Qpsh, W2th, h, BR + BR_V(5 + l),
                                          NTOT, 256, NF, 256, 1);
    }
}